// round 15
// baseline (speedup 1.0000x reference)
#include <cuda_runtime.h>
#include <cuda_fp16.h>
#include <math.h>
#include <stdint.h>

// ---------------------------------------------------------------------------
// PairwiseAttention round 12: round-11 pipeline (92.2us best) with proj
// rebuilt for latency overlap: 64-row tiles (grid 1024), z-residual staged
// through smem, 32x32 warp tiles. ln_cast / QKV GEMM / attn unchanged.
// ---------------------------------------------------------------------------

#define L 256
#define D 128
#define NH 4
#define HD 32
#define M_TOTAL (L * L)          // 65536
#define QKV_N (3 * D)            // 384
#define QSCALE 0.17677669529663687f   // 1/sqrt(32)
#define LOG2E 1.4426950408889634f
#define EOFF 8.0f                // e = 2^(s*log2e - EOFF); cancels in o/l

// Scratch
__device__ __half g_zn[(size_t)M_TOTAL * D];
__device__ __half g_qkv[(size_t)M_TOTAL * QKV_N];   // Q pre-scaled
__device__ __half g_o[(size_t)M_TOTAL * D];
__device__ __half g_wq[D * QKV_N];
__device__ __half g_wp[D * D];

// ---- helpers --------------------------------------------------------------
__device__ __forceinline__ uint32_t smem_u32(const void* p) {
    return (uint32_t)__cvta_generic_to_shared(p);
}
__device__ __forceinline__ void ldmx4(uint32_t* r, uint32_t a) {
    asm volatile("ldmatrix.sync.aligned.m8n8.x4.shared.b16 {%0,%1,%2,%3}, [%4];"
                 : "=r"(r[0]), "=r"(r[1]), "=r"(r[2]), "=r"(r[3]) : "r"(a));
}
__device__ __forceinline__ void ldmx4t(uint32_t* r, uint32_t a) {
    asm volatile("ldmatrix.sync.aligned.m8n8.x4.trans.shared.b16 {%0,%1,%2,%3}, [%4];"
                 : "=r"(r[0]), "=r"(r[1]), "=r"(r[2]), "=r"(r[3]) : "r"(a));
}
__device__ __forceinline__ void mma16816(float* d, const uint32_t* a, const uint32_t* b) {
    asm volatile(
        "mma.sync.aligned.m16n8k16.row.col.f32.f16.f16.f32 "
        "{%0,%1,%2,%3}, {%4,%5,%6,%7}, {%8,%9}, {%0,%1,%2,%3};"
        : "+f"(d[0]), "+f"(d[1]), "+f"(d[2]), "+f"(d[3])
        : "r"(a[0]), "r"(a[1]), "r"(a[2]), "r"(a[3]), "r"(b[0]), "r"(b[1]));
}
__device__ __forceinline__ uint32_t packh2(float x, float y) {
    __half2 t = __floats2half2_rn(x, y);
    return *(uint32_t*)&t;
}
__device__ __forceinline__ uint32_t ex2h2(uint32_t p) {
    uint32_t e;
    asm("ex2.approx.f16x2 %0, %1;" : "=r"(e) : "r"(p));
    return e;
}

// ---------------------------------------------------------------------------
// Merged LN + weight-cast kernel (unchanged from round 11).
// ---------------------------------------------------------------------------
#define LN_BLOCKS (M_TOTAL / 8)
#define CAST_BLOCKS ((D * QKV_N + D * D + 255) / 256)

__global__ void ln_cast_kernel(const float* __restrict__ z,
                               const float* __restrict__ g,
                               const float* __restrict__ b,
                               const float* __restrict__ wq,
                               const float* __restrict__ wp) {
    int bid = blockIdx.x;
    if (bid < LN_BLOCKS) {
        int pos  = bid * 8 + (threadIdx.x >> 5);
        int lane = threadIdx.x & 31;
        const float* zp = z + (size_t)pos * D;

        float4 v = *(const float4*)&zp[lane * 4];
        float s = v.x + v.y + v.z + v.w;
        #pragma unroll
        for (int o = 16; o; o >>= 1) s += __shfl_xor_sync(0xffffffffu, s, o);
        float mu = s * (1.0f / 128.0f);

        float dx = v.x - mu, dy = v.y - mu, dz = v.z - mu, dw = v.w - mu;
        float q = dx * dx + dy * dy + dz * dz + dw * dw;
        #pragma unroll
        for (int o = 16; o; o >>= 1) q += __shfl_xor_sync(0xffffffffu, q, o);
        float rstd = rsqrtf(q * (1.0f / 128.0f) + 1e-5f);

        float4 gg = *(const float4*)&g[lane * 4];
        float4 bb = *(const float4*)&b[lane * 4];
        uint2 o2;
        o2.x = packh2(dx * rstd * gg.x + bb.x, dy * rstd * gg.y + bb.y);
        o2.y = packh2(dz * rstd * gg.z + bb.z, dw * rstd * gg.w + bb.w);
        *(uint2*)&g_zn[(size_t)pos * D + lane * 4] = o2;
    } else {
        int i = (bid - LN_BLOCKS) * 256 + threadIdx.x;
        if (i < D * QKV_N) g_wq[i] = __float2half_rn(wq[i]);
        else {
            int j = i - D * QKV_N;
            if (j < D * D) g_wp[j] = __float2half_rn(wp[j]);
        }
    }
}

// ---------------------------------------------------------------------------
// QKV GEMM (unchanged from round 11): C = zn @ Wq + b, fp16 out, Q scaled.
// Block 128x128, 256 threads, 2x4 warps, warp tile 64x32. smem 64 KB.
// ---------------------------------------------------------------------------
__global__ __launch_bounds__(256, 2)
void qkv_gemm_kernel(const float* __restrict__ bias) {
    constexpr int N = QKV_N;
    extern __shared__ char sm_raw[];
    __half* As = (__half*)sm_raw;            // 128x128
    __half* Bs = As + 128 * 128;

    int tid = threadIdx.x;
    int m0 = blockIdx.y * 128;
    int n0 = blockIdx.x * 128;

    #pragma unroll
    for (int i = 0; i < 8; i++) {
        int idx = tid + i * 256;
        int m = idx >> 4, c = idx & 15;
        *(uint4*)&As[m * 128 + ((c ^ (m & 7)) * 8)] =
            *(const uint4*)&g_zn[(size_t)(m0 + m) * D + c * 8];
    }
    #pragma unroll
    for (int i = 0; i < 8; i++) {
        int idx = tid + i * 256;
        int k = idx >> 4, c = idx & 15;
        *(uint4*)&Bs[k * 128 + ((c ^ (k & 7)) * 8)] =
            *(const uint4*)&g_wq[(size_t)k * N + n0 + c * 8];
    }
    __syncthreads();

    int w = tid >> 5, l = tid & 31;
    int mw = (w >> 2) * 64, nw = (w & 3) * 32;
    int sel = l >> 3, li = l & 7;

    uint32_t Abase = smem_u32(As);
    uint32_t Bbase = smem_u32(Bs);

    float acc[4][4][4];
    #pragma unroll
    for (int mt = 0; mt < 4; mt++)
        #pragma unroll
        for (int nt = 0; nt < 4; nt++)
            #pragma unroll
            for (int j = 0; j < 4; j++) acc[mt][nt][j] = 0.0f;

    #pragma unroll
    for (int kt = 0; kt < 8; kt++) {
        uint32_t af[4][4];
        #pragma unroll
        for (int mt = 0; mt < 4; mt++) {
            int m = mw + mt * 16 + li + ((sel & 1) << 3);
            int kc = kt * 2 + (sel >> 1);
            ldmx4(af[mt], Abase + (uint32_t)(m * 128 + ((kc ^ (m & 7)) * 8)) * 2);
        }
        uint32_t bf_[4][2];
        #pragma unroll
        for (int p = 0; p < 2; p++) {
            int k = kt * 16 + ((sel & 1) << 3) + li;
            int nc = (nw >> 3) + p * 2 + (sel >> 1);
            uint32_t t[4];
            ldmx4t(t, Bbase + (uint32_t)(k * 128 + ((nc ^ (k & 7)) * 8)) * 2);
            bf_[2 * p][0] = t[0]; bf_[2 * p][1] = t[1];
            bf_[2 * p + 1][0] = t[2]; bf_[2 * p + 1][1] = t[3];
        }
        #pragma unroll
        for (int mt = 0; mt < 4; mt++)
            #pragma unroll
            for (int nt = 0; nt < 4; nt++)
                mma16816(acc[mt][nt], af[mt], bf_[nt]);
    }

    int grp = l >> 2, qd = l & 3;
    #pragma unroll
    for (int mt = 0; mt < 4; mt++) {
        #pragma unroll
        for (int nt = 0; nt < 4; nt++) {
            int gm = m0 + mw + mt * 16 + grp;
            int gn = n0 + nw + nt * 8 + qd * 2;
            float b0 = bias[gn], b1 = bias[gn + 1];
            float sc = (gn < D) ? QSCALE : 1.0f;
            *(uint32_t*)&g_qkv[(size_t)gm * N + gn] =
                packh2((acc[mt][nt][0] + b0) * sc, (acc[mt][nt][1] + b1) * sc);
            *(uint32_t*)&g_qkv[(size_t)(gm + 8) * N + gn] =
                packh2((acc[mt][nt][2] + b0) * sc, (acc[mt][nt][3] + b1) * sc);
        }
    }
}

// ---------------------------------------------------------------------------
// Proj kernel, rebuilt: 64-row tiles (grid 1024), z staged via smem,
// 2x4 warps with 32x32 warp tiles. smem 80 KB (As 16K + Bs 32K + Zs 32K).
// out = g_o @ Wp + b + z  (fp32).
// ---------------------------------------------------------------------------
__global__ __launch_bounds__(256, 2)
void proj_kernel(const float* __restrict__ bias,
                 const float* __restrict__ Zr,
                 float* __restrict__ Cout) {
    extern __shared__ char sm_raw[];
    __half* As = (__half*)sm_raw;                    // 64x128 fp16 swizzled
    __half* Bs = As + 64 * 128;                      // 128x128 fp16 swizzled
    float*  Zs = (float*)(Bs + 128 * 128);           // 64x128 fp32 plain

    int tid = threadIdx.x;
    int m0 = blockIdx.x * 64;

    // stage A: 64 rows x 16 chunks = 1024 uint4
    #pragma unroll
    for (int i = 0; i < 4; i++) {
        int idx = tid + i * 256;
        int m = idx >> 4, c = idx & 15;
        *(uint4*)&As[m * 128 + ((c ^ (m & 7)) * 8)] =
            *(const uint4*)&g_o[(size_t)(m0 + m) * D + c * 8];
    }
    // stage B: 128 rows x 16 chunks = 2048 uint4
    #pragma unroll
    for (int i = 0; i < 8; i++) {
        int idx = tid + i * 256;
        int k = idx >> 4, c = idx & 15;
        *(uint4*)&Bs[k * 128 + ((c ^ (k & 7)) * 8)] =
            *(const uint4*)&g_wp[(size_t)k * D + c * 8];
    }
    // stage Z residual: 64 rows x 32 float4 = 2048 float4
    #pragma unroll
    for (int i = 0; i < 8; i++) {
        int idx = tid + i * 256;
        int m = idx >> 5, q = idx & 31;
        *(float4*)&Zs[m * 128 + q * 4] =
            *(const float4*)&Zr[(size_t)(m0 + m) * D + q * 4];
    }
    __syncthreads();

    int w = tid >> 5, l = tid & 31;
    int mw = (w >> 2) * 32, nw = (w & 3) * 32;
    int sel = l >> 3, li = l & 7;

    uint32_t Abase = smem_u32(As);
    uint32_t Bbase = smem_u32(Bs);

    float acc[2][4][4];
    #pragma unroll
    for (int mt = 0; mt < 2; mt++)
        #pragma unroll
        for (int nt = 0; nt < 4; nt++)
            #pragma unroll
            for (int j = 0; j < 4; j++) acc[mt][nt][j] = 0.0f;

    #pragma unroll
    for (int kt = 0; kt < 8; kt++) {
        uint32_t af[2][4];
        #pragma unroll
        for (int mt = 0; mt < 2; mt++) {
            int m = mw + mt * 16 + li + ((sel & 1) << 3);
            int kc = kt * 2 + (sel >> 1);
            ldmx4(af[mt], Abase + (uint32_t)(m * 128 + ((kc ^ (m & 7)) * 8)) * 2);
        }
        uint32_t bf_[4][2];
        #pragma unroll
        for (int p = 0; p < 2; p++) {
            int k = kt * 16 + ((sel & 1) << 3) + li;
            int nc = (nw >> 3) + p * 2 + (sel >> 1);
            uint32_t t[4];
            ldmx4t(t, Bbase + (uint32_t)(k * 128 + ((nc ^ (k & 7)) * 8)) * 2);
            bf_[2 * p][0] = t[0]; bf_[2 * p][1] = t[1];
            bf_[2 * p + 1][0] = t[2]; bf_[2 * p + 1][1] = t[3];
        }
        #pragma unroll
        for (int mt = 0; mt < 2; mt++)
            #pragma unroll
            for (int nt = 0; nt < 4; nt++)
                mma16816(acc[mt][nt], af[mt], bf_[nt]);
    }

    int grp = l >> 2, qd = l & 3;
    #pragma unroll
    for (int mt = 0; mt < 2; mt++) {
        #pragma unroll
        for (int nt = 0; nt < 4; nt++) {
            int lm = mw + mt * 16 + grp;          // local row in tile
            int gn = nw + nt * 8 + qd * 2;
            int gm = m0 + lm;
            float b0 = bias[gn], b1 = bias[gn + 1];
            float2 r0 = *(const float2*)&Zs[lm * 128 + gn];
            float2 r1 = *(const float2*)&Zs[(lm + 8) * 128 + gn];
            *(float2*)&Cout[(size_t)gm * D + gn] =
                make_float2(acc[mt][nt][0] + b0 + r0.x, acc[mt][nt][1] + b1 + r0.y);
            *(float2*)&Cout[(size_t)(gm + 8) * D + gn] =
                make_float2(acc[mt][nt][2] + b0 + r1.x, acc[mt][nt][3] + b1 + r1.y);
        }
    }
}

// ---------------------------------------------------------------------------
// Attention (unchanged from round 11): block per (h, r), 8 warps x 32 q,
// offset softmax, V-fragments hoisted before the exp chain. smem 60 KB.
// ---------------------------------------------------------------------------
#define APITCH 40
__global__ __launch_bounds__(256, 2)
void attn_kernel() {
    extern __shared__ char sm_raw[];
    __half* Qs = (__half*)sm_raw;            // 256 * 40
    __half* Ks = Qs + 256 * APITCH;
    __half* Vs = Ks + 256 * APITCH;

    int h = blockIdx.x;
    int r = blockIdx.y;
    int tid = threadIdx.x;
    size_t mbase = (size_t)r * L;

    #pragma unroll
    for (int mat = 0; mat < 3; mat++) {
        __half* dst = (mat == 0) ? Qs : (mat == 1) ? Ks : Vs;
        int col0 = mat * D + h * HD;
        #pragma unroll
        for (int i = 0; i < 4; i++) {
            int idx = tid + i * 256;
            int pos = idx >> 2, c = idx & 3;
            *(uint4*)&dst[pos * APITCH + c * 8] =
                *(const uint4*)&g_qkv[(mbase + pos) * QKV_N + col0 + c * 8];
        }
    }
    __syncthreads();

    int w = tid >> 5, l = tid & 31;
    int q0 = w * 32;
    int sel = l >> 3, li = l & 7, grp = l >> 2, qd = l & 3;

    uint32_t Qbase = smem_u32(Qs);
    uint32_t Kbase = smem_u32(Ks);
    uint32_t Vbase = smem_u32(Vs);

    uint32_t qf[2][2][4];
    #pragma unroll
    for (int kk = 0; kk < 2; kk++)
        #pragma unroll
        for (int mt = 0; mt < 2; mt++) {
            int m = q0 + mt * 16 + li + ((sel & 1) << 3);
            int kc = kk * 2 + (sel >> 1);
            ldmx4(qf[kk][mt], Qbase + (uint32_t)(m * APITCH + kc * 8) * 2);
        }

    float lacc[2][2] = {{0.0f, 0.0f}, {0.0f, 0.0f}};   // [mt][row-half]
    float o[2][4][4];
    #pragma unroll
    for (int mt = 0; mt < 2; mt++)
        #pragma unroll
        for (int nt = 0; nt < 4; nt++)
            #pragma unroll
            for (int j = 0; j < 4; j++) o[mt][nt][j] = 0.0f;

    #pragma unroll 1
    for (int t = 0; t < 8; t++) {             // key tiles of 32
        float s[2][4][4];
        #pragma unroll
        for (int mt = 0; mt < 2; mt++)
            #pragma unroll
            for (int nt = 0; nt < 4; nt++)
                #pragma unroll
                for (int j = 0; j < 4; j++) s[mt][nt][j] = 0.0f;

        #pragma unroll
        for (int kk = 0; kk < 2; kk++) {
            uint32_t kf[4][2];
            #pragma unroll
            for (int p = 0; p < 2; p++) {
                int key = t * 32 + p * 16 + ((sel >> 1) << 3) + li;
                int dc = kk * 2 + (sel & 1);
                uint32_t tr[4];
                ldmx4(tr, Kbase + (uint32_t)(key * APITCH + dc * 8) * 2);
                kf[2 * p][0] = tr[0]; kf[2 * p][1] = tr[1];
                kf[2 * p + 1][0] = tr[2]; kf[2 * p + 1][1] = tr[3];
            }
            #pragma unroll
            for (int mt = 0; mt < 2; mt++)
                #pragma unroll
                for (int nt = 0; nt < 4; nt++)
                    mma16816(s[mt][nt], qf[kk][mt], kf[nt]);
        }

        // V fragments for both k16 halves, loaded early
        uint32_t vf[2][4][2];
        #pragma unroll
        for (int kt = 0; kt < 2; kt++)
            #pragma unroll
            for (int p = 0; p < 2; p++) {
                int key = t * 32 + kt * 16 + ((sel & 1) << 3) + li;
                int dc = p * 2 + (sel >> 1);
                uint32_t tr[4];
                ldmx4t(tr, Vbase + (uint32_t)(key * APITCH + dc * 8) * 2);
                vf[kt][2 * p][0] = tr[0]; vf[kt][2 * p][1] = tr[1];
                vf[kt][2 * p + 1][0] = tr[2]; vf[kt][2 * p + 1][1] = tr[3];
            }

        uint32_t pe[2][4][2];     // [mt][nt][row-half]
        #pragma unroll
        for (int mt = 0; mt < 2; mt++)
            #pragma unroll
            for (int nt = 0; nt < 4; nt++)
                #pragma unroll
                for (int hf = 0; hf < 2; hf++) {
                    float x0 = s[mt][nt][2 * hf] * LOG2E - EOFF;
                    float x1 = s[mt][nt][2 * hf + 1] * LOG2E - EOFF;
                    pe[mt][nt][hf] = ex2h2(packh2(x0, x1));
                }

        #pragma unroll
        for (int mt = 0; mt < 2; mt++)
            #pragma unroll
            for (int hf = 0; hf < 2; hf++) {
                __half2 a = *(__half2*)&pe[mt][0][hf];
                __half2 b = *(__half2*)&pe[mt][1][hf];
                __half2 c = *(__half2*)&pe[mt][2][hf];
                __half2 d = *(__half2*)&pe[mt][3][hf];
                __half2 sum = __hadd2(__hadd2(a, b), __hadd2(c, d));
                float2 f = __half22float2(sum);
                lacc[mt][hf] += f.x + f.y;
            }

        #pragma unroll
        for (int kt = 0; kt < 2; kt++) {
            uint32_t pa[2][4];
            #pragma unroll
            for (int mt = 0; mt < 2; mt++)
                #pragma unroll
                for (int j = 0; j < 4; j++)
                    pa[mt][j] = pe[mt][2 * kt + (j >> 1)][j & 1];
            #pragma unroll
            for (int mt = 0; mt < 2; mt++)
                #pragma unroll
                for (int nt = 0; nt < 4; nt++)
                    mma16816(o[mt][nt], pa[mt], vf[kt][nt]);
        }
    }

    #pragma unroll
    for (int mt = 0; mt < 2; mt++)
        #pragma unroll
        for (int hf = 0; hf < 2; hf++) {
            float v = lacc[mt][hf];
            v += __shfl_xor_sync(0xffffffffu, v, 1);
            v += __shfl_xor_sync(0xffffffffu, v, 2);
            lacc[mt][hf] = v;
        }

    #pragma unroll
    for (int mt = 0; mt < 2; mt++) {
        float inv0 = 1.0f / lacc[mt][0];
        float inv1 = 1.0f / lacc[mt][1];
        #pragma unroll
        for (int nt = 0; nt < 4; nt++) {
            int q = q0 + mt * 16 + grp;
            int d = nt * 8 + qd * 2;
            size_t off0 = (mbase + q) * D + h * HD + d;
            size_t off1 = (mbase + q + 8) * D + h * HD + d;
            *(uint32_t*)&g_o[off0] = packh2(o[mt][nt][0] * inv0, o[mt][nt][1] * inv0);
            *(uint32_t*)&g_o[off1] = packh2(o[mt][nt][2] * inv1, o[mt][nt][3] * inv1);
        }
    }
}

// ---------------------------------------------------------------------------
// Launch
// ---------------------------------------------------------------------------
extern "C" void kernel_launch(void* const* d_in, const int* in_sizes, int n_in,
                              void* d_out, int out_size) {
    const float* z      = (const float*)d_in[0];
    const float* ln_g   = (const float*)d_in[1];
    const float* ln_b   = (const float*)d_in[2];
    const float* w_qkv  = (const float*)d_in[3];
    const float* b_qkv  = (const float*)d_in[4];
    const float* w_proj = (const float*)d_in[5];
    const float* b_proj = (const float*)d_in[6];
    float* out = (float*)d_out;

    const int GEMM_SMEM = 2 * 128 * 128 * 2;                 // 65536 B
    const int PROJ_SMEM = 64*128*2 + 128*128*2 + 64*128*4;   // 81920 B
    const int ATTN_SMEM = 3 * 256 * APITCH * 2;              // 61440 B
    cudaFuncSetAttribute(qkv_gemm_kernel,
                         cudaFuncAttributeMaxDynamicSharedMemorySize, GEMM_SMEM);
    cudaFuncSetAttribute(proj_kernel,
                         cudaFuncAttributeMaxDynamicSharedMemorySize, PROJ_SMEM);
    cudaFuncSetAttribute(attn_kernel,
                         cudaFuncAttributeMaxDynamicSharedMemorySize, ATTN_SMEM);

    // 1) LN -> zn fp16 and weight casts, one launch
    ln_cast_kernel<<<LN_BLOCKS + CAST_BLOCKS, 256>>>(z, ln_g, ln_b, w_qkv, w_proj);
    // 2) QKV GEMM -> fp16 (Q pre-scaled)
    qkv_gemm_kernel<<<dim3(QKV_N / 128, M_TOTAL / 128), 256, GEMM_SMEM>>>(b_qkv);
    // 3) attention -> O fp16
    attn_kernel<<<dim3(NH, L), 256, ATTN_SMEM>>>();
    // 4) proj + bias + residual -> out (fp32), 64-row tiles
    proj_kernel<<<M_TOTAL / 64, 256, PROJ_SMEM>>>(b_proj, z, out);
}

// round 16
// speedup vs baseline: 1.5041x; 1.5041x over previous
#include <cuda_runtime.h>
#include <cuda_fp16.h>
#include <math.h>
#include <stdint.h>

// ---------------------------------------------------------------------------
// PairwiseAttention round 13: exact round-11 pipeline (92.2us measured best)
// + one delta: proj warms L2 for the z-residual tile via prefetch.global.L2
// (round-12's smem-staging approach regressed; reverted).
// ---------------------------------------------------------------------------

#define L 256
#define D 128
#define NH 4
#define HD 32
#define M_TOTAL (L * L)          // 65536
#define QKV_N (3 * D)            // 384
#define QSCALE 0.17677669529663687f   // 1/sqrt(32)
#define LOG2E 1.4426950408889634f
#define EOFF 8.0f                // e = 2^(s*log2e - EOFF); cancels in o/l

// Scratch
__device__ __half g_zn[(size_t)M_TOTAL * D];
__device__ __half g_qkv[(size_t)M_TOTAL * QKV_N];   // Q pre-scaled
__device__ __half g_o[(size_t)M_TOTAL * D];
__device__ __half g_wq[D * QKV_N];
__device__ __half g_wp[D * D];

// ---- helpers --------------------------------------------------------------
__device__ __forceinline__ uint32_t smem_u32(const void* p) {
    return (uint32_t)__cvta_generic_to_shared(p);
}
__device__ __forceinline__ void ldmx4(uint32_t* r, uint32_t a) {
    asm volatile("ldmatrix.sync.aligned.m8n8.x4.shared.b16 {%0,%1,%2,%3}, [%4];"
                 : "=r"(r[0]), "=r"(r[1]), "=r"(r[2]), "=r"(r[3]) : "r"(a));
}
__device__ __forceinline__ void ldmx4t(uint32_t* r, uint32_t a) {
    asm volatile("ldmatrix.sync.aligned.m8n8.x4.trans.shared.b16 {%0,%1,%2,%3}, [%4];"
                 : "=r"(r[0]), "=r"(r[1]), "=r"(r[2]), "=r"(r[3]) : "r"(a));
}
__device__ __forceinline__ void mma16816(float* d, const uint32_t* a, const uint32_t* b) {
    asm volatile(
        "mma.sync.aligned.m16n8k16.row.col.f32.f16.f16.f32 "
        "{%0,%1,%2,%3}, {%4,%5,%6,%7}, {%8,%9}, {%0,%1,%2,%3};"
        : "+f"(d[0]), "+f"(d[1]), "+f"(d[2]), "+f"(d[3])
        : "r"(a[0]), "r"(a[1]), "r"(a[2]), "r"(a[3]), "r"(b[0]), "r"(b[1]));
}
__device__ __forceinline__ uint32_t packh2(float x, float y) {
    __half2 t = __floats2half2_rn(x, y);
    return *(uint32_t*)&t;
}
__device__ __forceinline__ uint32_t ex2h2(uint32_t p) {
    uint32_t e;
    asm("ex2.approx.f16x2 %0, %1;" : "=r"(e) : "r"(p));
    return e;
}

// ---------------------------------------------------------------------------
// Merged LN + weight-cast kernel.
// ---------------------------------------------------------------------------
#define LN_BLOCKS (M_TOTAL / 8)
#define CAST_BLOCKS ((D * QKV_N + D * D + 255) / 256)

__global__ void ln_cast_kernel(const float* __restrict__ z,
                               const float* __restrict__ g,
                               const float* __restrict__ b,
                               const float* __restrict__ wq,
                               const float* __restrict__ wp) {
    int bid = blockIdx.x;
    if (bid < LN_BLOCKS) {
        int pos  = bid * 8 + (threadIdx.x >> 5);
        int lane = threadIdx.x & 31;
        const float* zp = z + (size_t)pos * D;

        float4 v = *(const float4*)&zp[lane * 4];
        float s = v.x + v.y + v.z + v.w;
        #pragma unroll
        for (int o = 16; o; o >>= 1) s += __shfl_xor_sync(0xffffffffu, s, o);
        float mu = s * (1.0f / 128.0f);

        float dx = v.x - mu, dy = v.y - mu, dz = v.z - mu, dw = v.w - mu;
        float q = dx * dx + dy * dy + dz * dz + dw * dw;
        #pragma unroll
        for (int o = 16; o; o >>= 1) q += __shfl_xor_sync(0xffffffffu, q, o);
        float rstd = rsqrtf(q * (1.0f / 128.0f) + 1e-5f);

        float4 gg = *(const float4*)&g[lane * 4];
        float4 bb = *(const float4*)&b[lane * 4];
        uint2 o2;
        o2.x = packh2(dx * rstd * gg.x + bb.x, dy * rstd * gg.y + bb.y);
        o2.y = packh2(dz * rstd * gg.z + bb.z, dw * rstd * gg.w + bb.w);
        *(uint2*)&g_zn[(size_t)pos * D + lane * 4] = o2;
    } else {
        int i = (bid - LN_BLOCKS) * 256 + threadIdx.x;
        if (i < D * QKV_N) g_wq[i] = __float2half_rn(wq[i]);
        else {
            int j = i - D * QKV_N;
            if (j < D * D) g_wp[j] = __float2half_rn(wp[j]);
        }
    }
}

// ---------------------------------------------------------------------------
// GEMM: C[M x N] = A[M x 128] @ W[128 x N] (single fp16 pass).
// Block 128x128, 256 threads (2x4 warps, 64x32 warp tile). smem 64 KB.
// Rows 256B = 16 chunks of 16B, swizzle chunk c -> c ^ (row & 7).
// MODE 0: A=g_zn, W=g_wq, C=g_qkv fp16 (+bias, Q cols pre-scaled), N=384
// MODE 1: A=g_o,  W=g_wp, C=out fp32 (+bias +z residual, L2-prefetched)
// ---------------------------------------------------------------------------
template<int MODE>
__global__ __launch_bounds__(256, 2)
void gemm_kernel(const float* __restrict__ bias,
                 const float* __restrict__ Zr,
                 float* __restrict__ Cout) {
    constexpr int N = (MODE == 0) ? QKV_N : D;
    extern __shared__ char sm_raw[];
    __half* As = (__half*)sm_raw;            // 128x128
    __half* Bs = As + 128 * 128;

    int tid = threadIdx.x;
    int m0 = blockIdx.y * 128;
    int n0 = blockIdx.x * 128;

    const __half* Ag = (MODE == 0) ? g_zn : g_o;
    const __half* Bg = (MODE == 0) ? g_wq : g_wp;

    #pragma unroll
    for (int i = 0; i < 8; i++) {
        int idx = tid + i * 256;
        int m = idx >> 4, c = idx & 15;
        *(uint4*)&As[m * 128 + ((c ^ (m & 7)) * 8)] =
            *(const uint4*)&Ag[(size_t)(m0 + m) * D + c * 8];
    }
    #pragma unroll
    for (int i = 0; i < 8; i++) {
        int idx = tid + i * 256;
        int k = idx >> 4, c = idx & 15;
        *(uint4*)&Bs[k * 128 + ((c ^ (k & 7)) * 8)] =
            *(const uint4*)&Bg[(size_t)k * N + n0 + c * 8];
    }

    // MODE 1: warm L2 with the z residual tile (128 rows x 512 B = 512
    // lines of 128 B; 2 prefetches per thread). These drain during the
    // MMA loop, so epilogue LDGs hit L2 instead of DRAM.
    if (MODE == 1) {
        const char* zb = (const char*)(Zr + (size_t)m0 * D);
        #pragma unroll
        for (int i = 0; i < 2; i++) {
            asm volatile("prefetch.global.L2 [%0];"
                         :: "l"(zb + (tid + i * 256) * 128));
        }
    }
    __syncthreads();

    int w = tid >> 5, l = tid & 31;
    int mw = (w >> 2) * 64, nw = (w & 3) * 32;
    int sel = l >> 3, li = l & 7;

    uint32_t Abase = smem_u32(As);
    uint32_t Bbase = smem_u32(Bs);

    float acc[4][4][4];
    #pragma unroll
    for (int mt = 0; mt < 4; mt++)
        #pragma unroll
        for (int nt = 0; nt < 4; nt++)
            #pragma unroll
            for (int j = 0; j < 4; j++) acc[mt][nt][j] = 0.0f;

    #pragma unroll
    for (int kt = 0; kt < 8; kt++) {
        uint32_t af[4][4];
        #pragma unroll
        for (int mt = 0; mt < 4; mt++) {
            int m = mw + mt * 16 + li + ((sel & 1) << 3);
            int kc = kt * 2 + (sel >> 1);
            ldmx4(af[mt], Abase + (uint32_t)(m * 128 + ((kc ^ (m & 7)) * 8)) * 2);
        }
        uint32_t bf_[4][2];
        #pragma unroll
        for (int p = 0; p < 2; p++) {
            int k = kt * 16 + ((sel & 1) << 3) + li;
            int nc = (nw >> 3) + p * 2 + (sel >> 1);
            uint32_t t[4];
            ldmx4t(t, Bbase + (uint32_t)(k * 128 + ((nc ^ (k & 7)) * 8)) * 2);
            bf_[2 * p][0] = t[0]; bf_[2 * p][1] = t[1];
            bf_[2 * p + 1][0] = t[2]; bf_[2 * p + 1][1] = t[3];
        }
        #pragma unroll
        for (int mt = 0; mt < 4; mt++)
            #pragma unroll
            for (int nt = 0; nt < 4; nt++)
                mma16816(acc[mt][nt], af[mt], bf_[nt]);
    }

    int grp = l >> 2, qd = l & 3;
    #pragma unroll
    for (int mt = 0; mt < 4; mt++) {
        #pragma unroll
        for (int nt = 0; nt < 4; nt++) {
            int gm = m0 + mw + mt * 16 + grp;
            int gn = n0 + nw + nt * 8 + qd * 2;
            float b0 = bias[gn], b1 = bias[gn + 1];
            float v0 = acc[mt][nt][0] + b0;
            float v1 = acc[mt][nt][1] + b1;
            float v2 = acc[mt][nt][2] + b0;
            float v3 = acc[mt][nt][3] + b1;
            if (MODE == 0) {
                float sc = (gn < D) ? QSCALE : 1.0f;
                *(uint32_t*)&g_qkv[(size_t)gm * N + gn] = packh2(v0 * sc, v1 * sc);
                *(uint32_t*)&g_qkv[(size_t)(gm + 8) * N + gn] = packh2(v2 * sc, v3 * sc);
            } else {
                float2 r0 = *(const float2*)&Zr[(size_t)gm * N + gn];
                float2 r1 = *(const float2*)&Zr[(size_t)(gm + 8) * N + gn];
                *(float2*)&Cout[(size_t)gm * N + gn] = make_float2(v0 + r0.x, v1 + r0.y);
                *(float2*)&Cout[(size_t)(gm + 8) * N + gn] = make_float2(v2 + r1.x, v3 + r1.y);
            }
        }
    }
}

// ---------------------------------------------------------------------------
// Attention: block per (h, r), 256 threads = 8 warps x 32 queries.
// Offset softmax, V-fragments hoisted before the exp chain. smem 60 KB.
// ---------------------------------------------------------------------------
#define APITCH 40
__global__ __launch_bounds__(256, 2)
void attn_kernel() {
    extern __shared__ char sm_raw[];
    __half* Qs = (__half*)sm_raw;            // 256 * 40
    __half* Ks = Qs + 256 * APITCH;
    __half* Vs = Ks + 256 * APITCH;

    int h = blockIdx.x;
    int r = blockIdx.y;
    int tid = threadIdx.x;
    size_t mbase = (size_t)r * L;

    #pragma unroll
    for (int mat = 0; mat < 3; mat++) {
        __half* dst = (mat == 0) ? Qs : (mat == 1) ? Ks : Vs;
        int col0 = mat * D + h * HD;
        #pragma unroll
        for (int i = 0; i < 4; i++) {
            int idx = tid + i * 256;
            int pos = idx >> 2, c = idx & 3;
            *(uint4*)&dst[pos * APITCH + c * 8] =
                *(const uint4*)&g_qkv[(mbase + pos) * QKV_N + col0 + c * 8];
        }
    }
    __syncthreads();

    int w = tid >> 5, l = tid & 31;
    int q0 = w * 32;
    int sel = l >> 3, li = l & 7, grp = l >> 2, qd = l & 3;

    uint32_t Qbase = smem_u32(Qs);
    uint32_t Kbase = smem_u32(Ks);
    uint32_t Vbase = smem_u32(Vs);

    uint32_t qf[2][2][4];
    #pragma unroll
    for (int kk = 0; kk < 2; kk++)
        #pragma unroll
        for (int mt = 0; mt < 2; mt++) {
            int m = q0 + mt * 16 + li + ((sel & 1) << 3);
            int kc = kk * 2 + (sel >> 1);
            ldmx4(qf[kk][mt], Qbase + (uint32_t)(m * APITCH + kc * 8) * 2);
        }

    float lacc[2][2] = {{0.0f, 0.0f}, {0.0f, 0.0f}};   // [mt][row-half]
    float o[2][4][4];
    #pragma unroll
    for (int mt = 0; mt < 2; mt++)
        #pragma unroll
        for (int nt = 0; nt < 4; nt++)
            #pragma unroll
            for (int j = 0; j < 4; j++) o[mt][nt][j] = 0.0f;

    #pragma unroll 1
    for (int t = 0; t < 8; t++) {             // key tiles of 32
        float s[2][4][4];
        #pragma unroll
        for (int mt = 0; mt < 2; mt++)
            #pragma unroll
            for (int nt = 0; nt < 4; nt++)
                #pragma unroll
                for (int j = 0; j < 4; j++) s[mt][nt][j] = 0.0f;

        #pragma unroll
        for (int kk = 0; kk < 2; kk++) {
            uint32_t kf[4][2];
            #pragma unroll
            for (int p = 0; p < 2; p++) {
                int key = t * 32 + p * 16 + ((sel >> 1) << 3) + li;
                int dc = kk * 2 + (sel & 1);
                uint32_t tr[4];
                ldmx4(tr, Kbase + (uint32_t)(key * APITCH + dc * 8) * 2);
                kf[2 * p][0] = tr[0]; kf[2 * p][1] = tr[1];
                kf[2 * p + 1][0] = tr[2]; kf[2 * p + 1][1] = tr[3];
            }
            #pragma unroll
            for (int mt = 0; mt < 2; mt++)
                #pragma unroll
                for (int nt = 0; nt < 4; nt++)
                    mma16816(s[mt][nt], qf[kk][mt], kf[nt]);
        }

        // V fragments for both k16 halves, loaded early
        uint32_t vf[2][4][2];
        #pragma unroll
        for (int kt = 0; kt < 2; kt++)
            #pragma unroll
            for (int p = 0; p < 2; p++) {
                int key = t * 32 + kt * 16 + ((sel & 1) << 3) + li;
                int dc = p * 2 + (sel >> 1);
                uint32_t tr[4];
                ldmx4t(tr, Vbase + (uint32_t)(key * APITCH + dc * 8) * 2);
                vf[kt][2 * p][0] = tr[0]; vf[kt][2 * p][1] = tr[1];
                vf[kt][2 * p + 1][0] = tr[2]; vf[kt][2 * p + 1][1] = tr[3];
            }

        uint32_t pe[2][4][2];     // [mt][nt][row-half]
        #pragma unroll
        for (int mt = 0; mt < 2; mt++)
            #pragma unroll
            for (int nt = 0; nt < 4; nt++)
                #pragma unroll
                for (int hf = 0; hf < 2; hf++) {
                    float x0 = s[mt][nt][2 * hf] * LOG2E - EOFF;
                    float x1 = s[mt][nt][2 * hf + 1] * LOG2E - EOFF;
                    pe[mt][nt][hf] = ex2h2(packh2(x0, x1));
                }

        #pragma unroll
        for (int mt = 0; mt < 2; mt++)
            #pragma unroll
            for (int hf = 0; hf < 2; hf++) {
                __half2 a = *(__half2*)&pe[mt][0][hf];
                __half2 b = *(__half2*)&pe[mt][1][hf];
                __half2 c = *(__half2*)&pe[mt][2][hf];
                __half2 d = *(__half2*)&pe[mt][3][hf];
                __half2 sum = __hadd2(__hadd2(a, b), __hadd2(c, d));
                float2 f = __half22float2(sum);
                lacc[mt][hf] += f.x + f.y;
            }

        #pragma unroll
        for (int kt = 0; kt < 2; kt++) {
            uint32_t pa[2][4];
            #pragma unroll
            for (int mt = 0; mt < 2; mt++)
                #pragma unroll
                for (int j = 0; j < 4; j++)
                    pa[mt][j] = pe[mt][2 * kt + (j >> 1)][j & 1];
            #pragma unroll
            for (int mt = 0; mt < 2; mt++)
                #pragma unroll
                for (int nt = 0; nt < 4; nt++)
                    mma16816(o[mt][nt], pa[mt], vf[kt][nt]);
        }
    }

    #pragma unroll
    for (int mt = 0; mt < 2; mt++)
        #pragma unroll
        for (int hf = 0; hf < 2; hf++) {
            float v = lacc[mt][hf];
            v += __shfl_xor_sync(0xffffffffu, v, 1);
            v += __shfl_xor_sync(0xffffffffu, v, 2);
            lacc[mt][hf] = v;
        }

    #pragma unroll
    for (int mt = 0; mt < 2; mt++) {
        float inv0 = 1.0f / lacc[mt][0];
        float inv1 = 1.0f / lacc[mt][1];
        #pragma unroll
        for (int nt = 0; nt < 4; nt++) {
            int q = q0 + mt * 16 + grp;
            int d = nt * 8 + qd * 2;
            size_t off0 = (mbase + q) * D + h * HD + d;
            size_t off1 = (mbase + q + 8) * D + h * HD + d;
            *(uint32_t*)&g_o[off0] = packh2(o[mt][nt][0] * inv0, o[mt][nt][1] * inv0);
            *(uint32_t*)&g_o[off1] = packh2(o[mt][nt][2] * inv1, o[mt][nt][3] * inv1);
        }
    }
}

// ---------------------------------------------------------------------------
// Launch
// ---------------------------------------------------------------------------
extern "C" void kernel_launch(void* const* d_in, const int* in_sizes, int n_in,
                              void* d_out, int out_size) {
    const float* z      = (const float*)d_in[0];
    const float* ln_g   = (const float*)d_in[1];
    const float* ln_b   = (const float*)d_in[2];
    const float* w_qkv  = (const float*)d_in[3];
    const float* b_qkv  = (const float*)d_in[4];
    const float* w_proj = (const float*)d_in[5];
    const float* b_proj = (const float*)d_in[6];
    float* out = (float*)d_out;

    const int GEMM_SMEM = 2 * 128 * 128 * 2;       //  65536 B
    const int ATTN_SMEM = 3 * 256 * APITCH * 2;    //  61440 B
    cudaFuncSetAttribute(gemm_kernel<0>,
                         cudaFuncAttributeMaxDynamicSharedMemorySize, GEMM_SMEM);
    cudaFuncSetAttribute(gemm_kernel<1>,
                         cudaFuncAttributeMaxDynamicSharedMemorySize, GEMM_SMEM);
    cudaFuncSetAttribute(attn_kernel,
                         cudaFuncAttributeMaxDynamicSharedMemorySize, ATTN_SMEM);

    // 1) LN -> zn fp16 and weight casts, one launch
    ln_cast_kernel<<<LN_BLOCKS + CAST_BLOCKS, 256>>>(z, ln_g, ln_b, w_qkv, w_proj);
    // 2) QKV GEMM -> fp16 (Q pre-scaled)
    gemm_kernel<0><<<dim3(QKV_N / 128, M_TOTAL / 128), 256, GEMM_SMEM>>>(
        b_qkv, nullptr, nullptr);
    // 3) attention -> O fp16
    attn_kernel<<<dim3(NH, L), 256, ATTN_SMEM>>>();
    // 4) proj + bias + residual -> out (fp32)
    gemm_kernel<1><<<dim3(1, M_TOTAL / 128), 256, GEMM_SMEM>>>(
        b_proj, z, out);
}

// round 17
// speedup vs baseline: 1.5639x; 1.0397x over previous
#include <cuda_runtime.h>
#include <cuda_fp16.h>
#include <math.h>
#include <stdint.h>

// ---------------------------------------------------------------------------
// PairwiseAttention round 14: round-11 pipeline (92.2us best) with ONE delta:
// g_qkv stored head-major [h][r][pos][mat*32+d] so each attention block reads
// one contiguous 48KB region (100% sector utilization vs ~50% before).
// Round-13 prefetch dropped (measured neutral).
// ---------------------------------------------------------------------------

#define L 256
#define D 128
#define NH 4
#define HD 32
#define M_TOTAL (L * L)          // 65536
#define QKV_N (3 * D)            // 384
#define QSCALE 0.17677669529663687f   // 1/sqrt(32)
#define LOG2E 1.4426950408889634f
#define EOFF 8.0f                // e = 2^(s*log2e - EOFF); cancels in o/l

// Scratch. g_qkv layout: ((h*L + r)*L + pos)*96 + mat*32 + d  (fp16)
__device__ __half g_zn[(size_t)M_TOTAL * D];
__device__ __half g_qkv[(size_t)M_TOTAL * QKV_N];
__device__ __half g_o[(size_t)M_TOTAL * D];
__device__ __half g_wq[D * QKV_N];
__device__ __half g_wp[D * D];

// ---- helpers --------------------------------------------------------------
__device__ __forceinline__ uint32_t smem_u32(const void* p) {
    return (uint32_t)__cvta_generic_to_shared(p);
}
__device__ __forceinline__ void ldmx4(uint32_t* r, uint32_t a) {
    asm volatile("ldmatrix.sync.aligned.m8n8.x4.shared.b16 {%0,%1,%2,%3}, [%4];"
                 : "=r"(r[0]), "=r"(r[1]), "=r"(r[2]), "=r"(r[3]) : "r"(a));
}
__device__ __forceinline__ void ldmx4t(uint32_t* r, uint32_t a) {
    asm volatile("ldmatrix.sync.aligned.m8n8.x4.trans.shared.b16 {%0,%1,%2,%3}, [%4];"
                 : "=r"(r[0]), "=r"(r[1]), "=r"(r[2]), "=r"(r[3]) : "r"(a));
}
__device__ __forceinline__ void mma16816(float* d, const uint32_t* a, const uint32_t* b) {
    asm volatile(
        "mma.sync.aligned.m16n8k16.row.col.f32.f16.f16.f32 "
        "{%0,%1,%2,%3}, {%4,%5,%6,%7}, {%8,%9}, {%0,%1,%2,%3};"
        : "+f"(d[0]), "+f"(d[1]), "+f"(d[2]), "+f"(d[3])
        : "r"(a[0]), "r"(a[1]), "r"(a[2]), "r"(a[3]), "r"(b[0]), "r"(b[1]));
}
__device__ __forceinline__ uint32_t packh2(float x, float y) {
    __half2 t = __floats2half2_rn(x, y);
    return *(uint32_t*)&t;
}
__device__ __forceinline__ uint32_t ex2h2(uint32_t p) {
    uint32_t e;
    asm("ex2.approx.f16x2 %0, %1;" : "=r"(e) : "r"(p));
    return e;
}

// ---------------------------------------------------------------------------
// Merged LN + weight-cast kernel (unchanged).
// ---------------------------------------------------------------------------
#define LN_BLOCKS (M_TOTAL / 8)
#define CAST_BLOCKS ((D * QKV_N + D * D + 255) / 256)

__global__ void ln_cast_kernel(const float* __restrict__ z,
                               const float* __restrict__ g,
                               const float* __restrict__ b,
                               const float* __restrict__ wq,
                               const float* __restrict__ wp) {
    int bid = blockIdx.x;
    if (bid < LN_BLOCKS) {
        int pos  = bid * 8 + (threadIdx.x >> 5);
        int lane = threadIdx.x & 31;
        const float* zp = z + (size_t)pos * D;

        float4 v = *(const float4*)&zp[lane * 4];
        float s = v.x + v.y + v.z + v.w;
        #pragma unroll
        for (int o = 16; o; o >>= 1) s += __shfl_xor_sync(0xffffffffu, s, o);
        float mu = s * (1.0f / 128.0f);

        float dx = v.x - mu, dy = v.y - mu, dz = v.z - mu, dw = v.w - mu;
        float q = dx * dx + dy * dy + dz * dz + dw * dw;
        #pragma unroll
        for (int o = 16; o; o >>= 1) q += __shfl_xor_sync(0xffffffffu, q, o);
        float rstd = rsqrtf(q * (1.0f / 128.0f) + 1e-5f);

        float4 gg = *(const float4*)&g[lane * 4];
        float4 bb = *(const float4*)&b[lane * 4];
        uint2 o2;
        o2.x = packh2(dx * rstd * gg.x + bb.x, dy * rstd * gg.y + bb.y);
        o2.y = packh2(dz * rstd * gg.z + bb.z, dw * rstd * gg.w + bb.w);
        *(uint2*)&g_zn[(size_t)pos * D + lane * 4] = o2;
    } else {
        int i = (bid - LN_BLOCKS) * 256 + threadIdx.x;
        if (i < D * QKV_N) g_wq[i] = __float2half_rn(wq[i]);
        else {
            int j = i - D * QKV_N;
            if (j < D * D) g_wp[j] = __float2half_rn(wp[j]);
        }
    }
}

// ---------------------------------------------------------------------------
// GEMM: C[M x N] = A[M x 128] @ W[128 x N] (single fp16 pass).
// Block 128x128, 256 threads (2x4 warps, 64x32 warp tile). smem 64 KB.
// Rows 256B = 16 chunks of 16B, swizzle chunk c -> c ^ (row & 7).
// MODE 0: A=g_zn, W=g_wq, C=g_qkv fp16 head-major (+bias, Q pre-scaled)
// MODE 1: A=g_o,  W=g_wp, C=out fp32 (+bias +z residual)
// ---------------------------------------------------------------------------
template<int MODE>
__global__ __launch_bounds__(256, 2)
void gemm_kernel(const float* __restrict__ bias,
                 const float* __restrict__ Zr,
                 float* __restrict__ Cout) {
    constexpr int N = (MODE == 0) ? QKV_N : D;
    extern __shared__ char sm_raw[];
    __half* As = (__half*)sm_raw;            // 128x128
    __half* Bs = As + 128 * 128;

    int tid = threadIdx.x;
    int m0 = blockIdx.y * 128;
    int n0 = blockIdx.x * 128;

    const __half* Ag = (MODE == 0) ? g_zn : g_o;
    const __half* Bg = (MODE == 0) ? g_wq : g_wp;

    #pragma unroll
    for (int i = 0; i < 8; i++) {
        int idx = tid + i * 256;
        int m = idx >> 4, c = idx & 15;
        *(uint4*)&As[m * 128 + ((c ^ (m & 7)) * 8)] =
            *(const uint4*)&Ag[(size_t)(m0 + m) * D + c * 8];
    }
    #pragma unroll
    for (int i = 0; i < 8; i++) {
        int idx = tid + i * 256;
        int k = idx >> 4, c = idx & 15;
        *(uint4*)&Bs[k * 128 + ((c ^ (k & 7)) * 8)] =
            *(const uint4*)&Bg[(size_t)k * N + n0 + c * 8];
    }
    __syncthreads();

    int w = tid >> 5, l = tid & 31;
    int mw = (w >> 2) * 64, nw = (w & 3) * 32;
    int sel = l >> 3, li = l & 7;

    uint32_t Abase = smem_u32(As);
    uint32_t Bbase = smem_u32(Bs);

    float acc[4][4][4];
    #pragma unroll
    for (int mt = 0; mt < 4; mt++)
        #pragma unroll
        for (int nt = 0; nt < 4; nt++)
            #pragma unroll
            for (int j = 0; j < 4; j++) acc[mt][nt][j] = 0.0f;

    #pragma unroll
    for (int kt = 0; kt < 8; kt++) {
        uint32_t af[4][4];
        #pragma unroll
        for (int mt = 0; mt < 4; mt++) {
            int m = mw + mt * 16 + li + ((sel & 1) << 3);
            int kc = kt * 2 + (sel >> 1);
            ldmx4(af[mt], Abase + (uint32_t)(m * 128 + ((kc ^ (m & 7)) * 8)) * 2);
        }
        uint32_t bf_[4][2];
        #pragma unroll
        for (int p = 0; p < 2; p++) {
            int k = kt * 16 + ((sel & 1) << 3) + li;
            int nc = (nw >> 3) + p * 2 + (sel >> 1);
            uint32_t t[4];
            ldmx4t(t, Bbase + (uint32_t)(k * 128 + ((nc ^ (k & 7)) * 8)) * 2);
            bf_[2 * p][0] = t[0]; bf_[2 * p][1] = t[1];
            bf_[2 * p + 1][0] = t[2]; bf_[2 * p + 1][1] = t[3];
        }
        #pragma unroll
        for (int mt = 0; mt < 4; mt++)
            #pragma unroll
            for (int nt = 0; nt < 4; nt++)
                mma16816(acc[mt][nt], af[mt], bf_[nt]);
    }

    int grp = l >> 2, qd = l & 3;
    #pragma unroll
    for (int mt = 0; mt < 4; mt++) {
        #pragma unroll
        for (int nt = 0; nt < 4; nt++) {
            int gm = m0 + mw + mt * 16 + grp;
            int gn = n0 + nw + nt * 8 + qd * 2;
            float b0 = bias[gn], b1 = bias[gn + 1];
            float v0 = acc[mt][nt][0] + b0;
            float v1 = acc[mt][nt][1] + b1;
            float v2 = acc[mt][nt][2] + b0;
            float v3 = acc[mt][nt][3] + b1;
            if (MODE == 0) {
                // head-major layout: ((hh*L + rr)*L + pos)*96 + mat*32 + d
                float sc = (gn < D) ? QSCALE : 1.0f;
                int mat = gn >> 7;
                int wc = gn & 127;
                int hh = wc >> 5, d = wc & 31;
                int rr = gm >> 8, pos = gm & 255;
                size_t base = ((size_t)(hh * L + rr) * L + pos) * 96 + mat * 32 + d;
                *(uint32_t*)&g_qkv[base] = packh2(v0 * sc, v1 * sc);
                *(uint32_t*)&g_qkv[base + 8 * 96] = packh2(v2 * sc, v3 * sc);
            } else {
                float2 r0 = *(const float2*)&Zr[(size_t)gm * N + gn];
                float2 r1 = *(const float2*)&Zr[(size_t)(gm + 8) * N + gn];
                *(float2*)&Cout[(size_t)gm * N + gn] = make_float2(v0 + r0.x, v1 + r0.y);
                *(float2*)&Cout[(size_t)(gm + 8) * N + gn] = make_float2(v2 + r1.x, v3 + r1.y);
            }
        }
    }
}

// ---------------------------------------------------------------------------
// Attention: block per (h, r), 256 threads = 8 warps x 32 queries.
// Offset softmax, V-fragments hoisted before the exp chain. smem 60 KB.
// Staging now reads ONE contiguous 48KB region (head-major g_qkv).
// ---------------------------------------------------------------------------
#define APITCH 40
__global__ __launch_bounds__(256, 2)
void attn_kernel() {
    extern __shared__ char sm_raw[];
    __half* Qs = (__half*)sm_raw;            // 256 * 40
    __half* Ks = Qs + 256 * APITCH;
    __half* Vs = Ks + 256 * APITCH;

    int h = blockIdx.x;
    int r = blockIdx.y;
    int tid = threadIdx.x;
    size_t mbase = (size_t)r * L;

    // contiguous block region: 256 pos x 96 halves
    const __half* src = g_qkv + ((size_t)(h * L + r) * L) * 96;
    #pragma unroll
    for (int mat = 0; mat < 3; mat++) {
        __half* dst = (mat == 0) ? Qs : (mat == 1) ? Ks : Vs;
        #pragma unroll
        for (int i = 0; i < 4; i++) {
            int idx = tid + i * 256;
            int pos = idx >> 2, c = idx & 3;
            *(uint4*)&dst[pos * APITCH + c * 8] =
                *(const uint4*)&src[(size_t)pos * 96 + mat * 32 + c * 8];
        }
    }
    __syncthreads();

    int w = tid >> 5, l = tid & 31;
    int q0 = w * 32;
    int sel = l >> 3, li = l & 7, grp = l >> 2, qd = l & 3;

    uint32_t Qbase = smem_u32(Qs);
    uint32_t Kbase = smem_u32(Ks);
    uint32_t Vbase = smem_u32(Vs);

    uint32_t qf[2][2][4];
    #pragma unroll
    for (int kk = 0; kk < 2; kk++)
        #pragma unroll
        for (int mt = 0; mt < 2; mt++) {
            int m = q0 + mt * 16 + li + ((sel & 1) << 3);
            int kc = kk * 2 + (sel >> 1);
            ldmx4(qf[kk][mt], Qbase + (uint32_t)(m * APITCH + kc * 8) * 2);
        }

    float lacc[2][2] = {{0.0f, 0.0f}, {0.0f, 0.0f}};   // [mt][row-half]
    float o[2][4][4];
    #pragma unroll
    for (int mt = 0; mt < 2; mt++)
        #pragma unroll
        for (int nt = 0; nt < 4; nt++)
            #pragma unroll
            for (int j = 0; j < 4; j++) o[mt][nt][j] = 0.0f;

    #pragma unroll 1
    for (int t = 0; t < 8; t++) {             // key tiles of 32
        float s[2][4][4];
        #pragma unroll
        for (int mt = 0; mt < 2; mt++)
            #pragma unroll
            for (int nt = 0; nt < 4; nt++)
                #pragma unroll
                for (int j = 0; j < 4; j++) s[mt][nt][j] = 0.0f;

        #pragma unroll
        for (int kk = 0; kk < 2; kk++) {
            uint32_t kf[4][2];
            #pragma unroll
            for (int p = 0; p < 2; p++) {
                int key = t * 32 + p * 16 + ((sel >> 1) << 3) + li;
                int dc = kk * 2 + (sel & 1);
                uint32_t tr[4];
                ldmx4(tr, Kbase + (uint32_t)(key * APITCH + dc * 8) * 2);
                kf[2 * p][0] = tr[0]; kf[2 * p][1] = tr[1];
                kf[2 * p + 1][0] = tr[2]; kf[2 * p + 1][1] = tr[3];
            }
            #pragma unroll
            for (int mt = 0; mt < 2; mt++)
                #pragma unroll
                for (int nt = 0; nt < 4; nt++)
                    mma16816(s[mt][nt], qf[kk][mt], kf[nt]);
        }

        // V fragments for both k16 halves, loaded early
        uint32_t vf[2][4][2];
        #pragma unroll
        for (int kt = 0; kt < 2; kt++)
            #pragma unroll
            for (int p = 0; p < 2; p++) {
                int key = t * 32 + kt * 16 + ((sel & 1) << 3) + li;
                int dc = p * 2 + (sel >> 1);
                uint32_t tr[4];
                ldmx4t(tr, Vbase + (uint32_t)(key * APITCH + dc * 8) * 2);
                vf[kt][2 * p][0] = tr[0]; vf[kt][2 * p][1] = tr[1];
                vf[kt][2 * p + 1][0] = tr[2]; vf[kt][2 * p + 1][1] = tr[3];
            }

        uint32_t pe[2][4][2];     // [mt][nt][row-half]
        #pragma unroll
        for (int mt = 0; mt < 2; mt++)
            #pragma unroll
            for (int nt = 0; nt < 4; nt++)
                #pragma unroll
                for (int hf = 0; hf < 2; hf++) {
                    float x0 = s[mt][nt][2 * hf] * LOG2E - EOFF;
                    float x1 = s[mt][nt][2 * hf + 1] * LOG2E - EOFF;
                    pe[mt][nt][hf] = ex2h2(packh2(x0, x1));
                }

        #pragma unroll
        for (int mt = 0; mt < 2; mt++)
            #pragma unroll
            for (int hf = 0; hf < 2; hf++) {
                __half2 a = *(__half2*)&pe[mt][0][hf];
                __half2 b = *(__half2*)&pe[mt][1][hf];
                __half2 c = *(__half2*)&pe[mt][2][hf];
                __half2 d = *(__half2*)&pe[mt][3][hf];
                __half2 sum = __hadd2(__hadd2(a, b), __hadd2(c, d));
                float2 f = __half22float2(sum);
                lacc[mt][hf] += f.x + f.y;
            }

        #pragma unroll
        for (int kt = 0; kt < 2; kt++) {
            uint32_t pa[2][4];
            #pragma unroll
            for (int mt = 0; mt < 2; mt++)
                #pragma unroll
                for (int j = 0; j < 4; j++)
                    pa[mt][j] = pe[mt][2 * kt + (j >> 1)][j & 1];
            #pragma unroll
            for (int mt = 0; mt < 2; mt++)
                #pragma unroll
                for (int nt = 0; nt < 4; nt++)
                    mma16816(o[mt][nt], pa[mt], vf[kt][nt]);
        }
    }

    #pragma unroll
    for (int mt = 0; mt < 2; mt++)
        #pragma unroll
        for (int hf = 0; hf < 2; hf++) {
            float v = lacc[mt][hf];
            v += __shfl_xor_sync(0xffffffffu, v, 1);
            v += __shfl_xor_sync(0xffffffffu, v, 2);
            lacc[mt][hf] = v;
        }

    #pragma unroll
    for (int mt = 0; mt < 2; mt++) {
        float inv0 = 1.0f / lacc[mt][0];
        float inv1 = 1.0f / lacc[mt][1];
        #pragma unroll
        for (int nt = 0; nt < 4; nt++) {
            int q = q0 + mt * 16 + grp;
            int d = nt * 8 + qd * 2;
            size_t off0 = (mbase + q) * D + h * HD + d;
            size_t off1 = (mbase + q + 8) * D + h * HD + d;
            *(uint32_t*)&g_o[off0] = packh2(o[mt][nt][0] * inv0, o[mt][nt][1] * inv0);
            *(uint32_t*)&g_o[off1] = packh2(o[mt][nt][2] * inv1, o[mt][nt][3] * inv1);
        }
    }
}

// ---------------------------------------------------------------------------
// Launch
// ---------------------------------------------------------------------------
extern "C" void kernel_launch(void* const* d_in, const int* in_sizes, int n_in,
                              void* d_out, int out_size) {
    const float* z      = (const float*)d_in[0];
    const float* ln_g   = (const float*)d_in[1];
    const float* ln_b   = (const float*)d_in[2];
    const float* w_qkv  = (const float*)d_in[3];
    const float* b_qkv  = (const float*)d_in[4];
    const float* w_proj = (const float*)d_in[5];
    const float* b_proj = (const float*)d_in[6];
    float* out = (float*)d_out;

    const int GEMM_SMEM = 2 * 128 * 128 * 2;       //  65536 B
    const int ATTN_SMEM = 3 * 256 * APITCH * 2;    //  61440 B
    cudaFuncSetAttribute(gemm_kernel<0>,
                         cudaFuncAttributeMaxDynamicSharedMemorySize, GEMM_SMEM);
    cudaFuncSetAttribute(gemm_kernel<1>,
                         cudaFuncAttributeMaxDynamicSharedMemorySize, GEMM_SMEM);
    cudaFuncSetAttribute(attn_kernel,
                         cudaFuncAttributeMaxDynamicSharedMemorySize, ATTN_SMEM);

    // 1) LN -> zn fp16 and weight casts, one launch
    ln_cast_kernel<<<LN_BLOCKS + CAST_BLOCKS, 256>>>(z, ln_g, ln_b, w_qkv, w_proj);
    // 2) QKV GEMM -> fp16 head-major (Q pre-scaled)
    gemm_kernel<0><<<dim3(QKV_N / 128, M_TOTAL / 128), 256, GEMM_SMEM>>>(
        b_qkv, nullptr, nullptr);
    // 3) attention -> O fp16
    attn_kernel<<<dim3(NH, L), 256, ATTN_SMEM>>>();
    // 4) proj + bias + residual -> out (fp32)
    gemm_kernel<1><<<dim3(1, M_TOTAL / 128), 256, GEMM_SMEM>>>(
        b_proj, z, out);
}